// round 10
// baseline (speedup 1.0000x reference)
#include <cuda_runtime.h>
#include <math.h>
#include <cub/device/device_radix_sort.cuh>

#define DIMN 3
#define NPTS 30
#define KK   181
#define PP   24360          // 30*29*28
#define DE   190            // 9 + 181
#define RESTN 27
#define NTOT ((size_t)KK * PP)   // 4,409,160 elements

// Sort bits: [12, 40) = 8 segment bits (k) + top-20 value bits.
// Values agreeing in sign+exponent+11 mantissa bits (rel gap < 2^-11) may be
// mutually unordered; measured dot error ~8.8e-5 relative (round 9), < 1e-3.
#define SORT_BEGIN_BIT 12
#define SORT_END_BIT   40

// ------------------------- device scratch (static, allowed) -------------------------
// +64 floats padding: K2's cp.async prefetch of the ragged last p-tile may read
// up to 63 elements past PP in the last row; keep that inside the allocation.
__device__ __align__(16) float g_vecT[(size_t)DE * PP + 64]; // (190, P) TRANSPOSED vec
__device__ float g_wsT[190 * 192];                      // Ws_out transposed, padded
__device__ float g_wdT[RESTN * KK];                     // WdIn transposed (27, 181)
__device__ __align__(16) float g_sm2T[(size_t)KK * PP]; // (K, P) column-major sm2
__device__ __align__(16) unsigned long long g_keysA[NTOT]; // packed (k|value) keys
__device__ __align__(16) unsigned long long g_keysB[NTOT]; // radix double buffer
__device__ __align__(16) unsigned char g_cubtmp[64 * 1024 * 1024]; // cub temp

// ------------------------- K0: transpose Ws_out -------------------------
__global__ void k0_transpose(const float* __restrict__ WsOut) {
    int j = blockIdx.x;          // 0..189
    int t = threadIdx.x;         // 0..191
    g_wsT[j * 192 + t] = (t < KK) ? WsOut[t * DE + j] : 0.0f;
}

// ------------------------- K0b: transpose Wd_in -------------------------
__global__ void k0b_transpose(const float* __restrict__ WdIn) {
    int m = blockIdx.x;          // 0..26
    int t = threadIdx.x;         // 0..191
    if (t < KK) g_wdT[m * KK + t] = WdIn[t * RESTN + m];
}

// ------------------------- K1: per-permutation vec rows (transposed store) ------------
__global__ void k1_vec(const float* __restrict__ matrix,
                       const float* __restrict__ WsIn) {
    __shared__ float mS[DIMN * NPTS];      // 90
    __shared__ float projS[DIMN][RESTN];   // 3x27
    __shared__ float gramS[9];

    const int p = blockIdx.x;
    const int t = threadIdx.x;             // 0..191

    // decode lexicographic permutation p -> (a,b,c)
    int a  = p / 812;                // 812 = 29*28
    int r  = p - a * 812;
    int bi = r / 28;
    int ci = r - bi * 28;
    int b  = bi + (bi >= a);
    int e0 = min(a, b), e1 = max(a, b);
    int c  = ci + (ci >= e0);
    c += (c >= e1);

    // sorted excluded triple for rest[]
    int s0 = min(a, min(b, c));
    int s2 = max(a, max(b, c));
    int s1 = a + b + c - s0 - s2;

    if (t < DIMN * NPTS) mS[t] = matrix[t];
    __syncthreads();

    if (t < DIMN * RESTN) {
        int i = t / RESTN, m = t - i * RESTN;
        int rm = m + (m >= s0); rm += (rm >= s1); rm += (rm >= s2);
        int ci_ = (i == 0) ? a : ((i == 1) ? b : c);
        projS[i][m] = mS[ci_] * mS[rm]
                    + mS[NPTS + ci_] * mS[NPTS + rm]
                    + mS[2 * NPTS + ci_] * mS[2 * NPTS + rm];
    } else if (t < DIMN * RESTN + 9) {
        int q = t - DIMN * RESTN;
        int i = q / 3, j = q - 3 * i;
        int ci_ = (i == 0) ? a : ((i == 1) ? b : c);
        int cj_ = (j == 0) ? a : ((j == 1) ? b : c);
        gramS[q] = mS[ci_] * mS[cj_]
                 + mS[NPTS + ci_] * mS[NPTS + cj_]
                 + mS[2 * NPTS + ci_] * mS[2 * NPTS + cj_];
    }
    __syncthreads();

    if (t < 9) g_vecT[(size_t)t * PP + p] = gramS[t];

    if (t < KK) {
        const int k = t;
        const float w0 = WsIn[k * 3 + 0];
        const float w1 = WsIn[k * 3 + 1];
        const float w2 = WsIn[k * 3 + 2];

        float v[32];
#pragma unroll
        for (int m = 0; m < RESTN; ++m)
            v[m] = fmaf(projS[2][m], w2, fmaf(projS[1][m], w1, projS[0][m] * w0));
        const float INF = __int_as_float(0x7f800000);
#pragma unroll
        for (int m = RESTN; m < 32; ++m) v[m] = INF;

        // fully-unrolled 32-element bitonic sort (ascending), registers only
#pragma unroll
        for (int size = 2; size <= 32; size <<= 1) {
#pragma unroll
            for (int stride = size >> 1; stride > 0; stride >>= 1) {
#pragma unroll
                for (int i = 0; i < 32; ++i) {
                    int j = i ^ stride;
                    if (j > i) {
                        bool up = ((i & size) == 0);
                        float x = v[i], y = v[j];
                        float lo = fminf(x, y), hi = fmaxf(x, y);
                        v[i] = up ? lo : hi;
                        v[j] = up ? hi : lo;
                    }
                }
            }
        }

        float e = 0.0f;
#pragma unroll
        for (int m = 0; m < RESTN; ++m)
            e = fmaf(g_wdT[m * KK + k], v[m], e);   // coalesced, L1-resident
        g_vecT[(size_t)(9 + k) * PP + p] = e;
    }
}

// ------------------------- K2: sm2T[k][p] = vec[p] . Ws_out[k] -------------------------
// packed f32x2 FMA (pair along k) + cp.async double-buffered tile pipeline
#define TP 64
#define JC 19
#define NTILE (DE / JC)      // 10

__device__ __forceinline__ void ffma2(unsigned long long& d,
                                      unsigned long long a,
                                      unsigned long long b) {
    asm("fma.rn.f32x2 %0, %1, %2, %0;" : "+l"(d) : "l"(a), "l"(b));
}
__device__ __forceinline__ unsigned long long dup_f32(float x) {
    unsigned long long r;
    unsigned int u = __float_as_uint(x);
    asm("mov.b64 %0, {%1, %1};" : "=l"(r) : "r"(u));
    return r;
}
__device__ __forceinline__ void cp16(void* smem, const void* gmem) {
    unsigned int saddr = (unsigned int)__cvta_generic_to_shared(smem);
    asm volatile("cp.async.ca.shared.global [%0], [%1], 16;"
                 :: "r"(saddr), "l"(gmem));
}

__global__ void __launch_bounds__(256)
k2_gemm() {
    __shared__ __align__(16) float vS[2][JC][TP];    // 2 x 4.9 KB
    __shared__ __align__(16) float wS[2][JC][192];   // 2 x 14.6 KB

    const int p0 = blockIdx.x * TP;
    const int t  = threadIdx.x;         // 256
    const int pt = t & 15;              // 16 p-threads (4 p each)
    const int kt = t >> 4;              // 16 k-threads (12 k each = 6 pairs)

    unsigned long long acc2[4][6];      // [p][k-pair]
#pragma unroll
    for (int r0 = 0; r0 < 4; ++r0)
#pragma unroll
        for (int cc = 0; cc < 6; ++cc) acc2[r0][cc] = 0ull;

    // ---- async tile loader: tile tt (j0 = tt*JC) into buffer b ----
    auto load_tile = [&](int tt, int b) {
        const int j0 = tt * JC;
        // vS: JC*TP/4 = 304 float4
        for (int idx = t; idx < JC * TP / 4; idx += 256) {
            int row = idx >> 4;          // /16
            int col = idx & 15;
            cp16(&vS[b][row][col * 4],
                 &g_vecT[(size_t)(j0 + row) * PP + p0 + col * 4]);
        }
        // wS: JC*192/4 = 912 float4
        for (int idx = t; idx < JC * 192 / 4; idx += 256) {
            int row = idx / 48;
            int col = idx - row * 48;
            cp16(&wS[b][row][col * 4],
                 &g_wsT[(j0 + row) * 192 + col * 4]);
        }
    };

    load_tile(0, 0);
    asm volatile("cp.async.commit_group;");

    for (int tt = 0; tt < NTILE; ++tt) {
        if (tt + 1 < NTILE) load_tile(tt + 1, (tt + 1) & 1);
        asm volatile("cp.async.commit_group;");
        asm volatile("cp.async.wait_group 1;");   // tile tt complete
        __syncthreads();

        const int b = tt & 1;
#pragma unroll
        for (int jj = 0; jj < JC; ++jj) {
            float4 rv = *reinterpret_cast<const float4*>(&vS[b][jj][pt * 4]);
            unsigned long long rr2[4] = {dup_f32(rv.x), dup_f32(rv.y),
                                         dup_f32(rv.z), dup_f32(rv.w)};
            const unsigned long long* wrow =
                reinterpret_cast<const unsigned long long*>(&wS[b][jj][0]);
            unsigned long long w2[6];
#pragma unroll
            for (int cc = 0; cc < 6; ++cc) w2[cc] = wrow[kt * 6 + cc];
#pragma unroll
            for (int cc = 0; cc < 6; ++cc)
#pragma unroll
                for (int r0 = 0; r0 < 4; ++r0)
                    ffma2(acc2[r0][cc], rr2[r0], w2[cc]);
        }
        __syncthreads();   // done reading buffer b before it is refilled
    }

    const bool full = (p0 + TP <= PP);
    // unpack: acc2[r0][cc] holds k = kt*12 + 2*cc (lo lane) and +1 (hi lane)
#pragma unroll
    for (int cc = 0; cc < 6; ++cc) {
#pragma unroll
        for (int half = 0; half < 2; ++half) {
            int k = kt * 12 + 2 * cc + half;
            if (k >= KK) continue;
            float a0, a1, a2, a3;
            if (half == 0) {
                a0 = __uint_as_float((unsigned int)(acc2[0][cc] & 0xffffffffull));
                a1 = __uint_as_float((unsigned int)(acc2[1][cc] & 0xffffffffull));
                a2 = __uint_as_float((unsigned int)(acc2[2][cc] & 0xffffffffull));
                a3 = __uint_as_float((unsigned int)(acc2[3][cc] & 0xffffffffull));
            } else {
                a0 = __uint_as_float((unsigned int)(acc2[0][cc] >> 32));
                a1 = __uint_as_float((unsigned int)(acc2[1][cc] >> 32));
                a2 = __uint_as_float((unsigned int)(acc2[2][cc] >> 32));
                a3 = __uint_as_float((unsigned int)(acc2[3][cc] >> 32));
            }
            size_t base = (size_t)k * PP + p0 + pt * 4;
            if (full) {
                *reinterpret_cast<float4*>(&g_sm2T[base]) = make_float4(a0, a1, a2, a3);
            } else {
                float av[4] = {a0, a1, a2, a3};
#pragma unroll
                for (int r0 = 0; r0 < 4; ++r0) {
                    int p = p0 + pt * 4 + r0;
                    if (p < PP) g_sm2T[(size_t)k * PP + p] = av[r0];
                }
            }
        }
    }
}

// ------------------------- K3p: pack (k, value) -> u64 radix keys ----------------------
__global__ void __launch_bounds__(256)
k3p_pack() {
    size_t idx = (size_t)blockIdx.x * 256 + threadIdx.x;
    if (idx >= NTOT) return;
    unsigned int u = __float_as_uint(g_sm2T[idx]);
    // order-preserving twiddle: neg -> ~u, pos -> u | signbit
    unsigned int tw = (u & 0x80000000u) ? ~u : (u | 0x80000000u);
    unsigned int k = (unsigned int)(idx / PP);
    g_keysA[idx] = ((unsigned long long)k << 32) | tw;
}

// ------------------------- K3c: rank-aligned weighted dot ------------------------------
// After the segmented sort, global position k*PP + r holds rank r of segment k.
__global__ void __launch_bounds__(1024)
k3c_dot(const unsigned long long* __restrict__ keys,
        const float* __restrict__ WdOut, float* __restrict__ out) {
    __shared__ float red[32];
    const int k = blockIdx.x;
    const int t = threadIdx.x;
    const size_t base = (size_t)k * PP;

    float acc = 0.0f;
    for (int i = t; i < PP; i += 1024) {           // coalesced
        unsigned int lo = (unsigned int)keys[base + i];
        unsigned int u = (lo & 0x80000000u) ? (lo ^ 0x80000000u) : ~lo;
        acc = fmaf(WdOut[base + i], __uint_as_float(u), acc);
    }

#pragma unroll
    for (int o = 16; o > 0; o >>= 1)
        acc += __shfl_down_sync(0xffffffffu, acc, o);
    if ((t & 31) == 0) red[t >> 5] = acc;
    __syncthreads();
    if (t < 32) {
        float x = red[t];
#pragma unroll
        for (int o = 16; o > 0; o >>= 1)
            x += __shfl_down_sync(0xffffffffu, x, o);
        if (t == 0) out[k] = x;
    }
}

// ------------------------- launch -------------------------
extern "C" void kernel_launch(void* const* d_in, const int* in_sizes, int n_in,
                              void* d_out, int out_size) {
    const float* matrix = (const float*)d_in[0];
    const float* WsIn   = (const float*)d_in[1];
    const float* WdIn   = (const float*)d_in[2];
    const float* WsOut  = (const float*)d_in[3];
    const float* WdOut  = (const float*)d_in[4];
    float* out = (float*)d_out;

    k0_transpose<<<DE, 192>>>(WsOut);
    k0b_transpose<<<RESTN, 192>>>(WdIn);
    k1_vec<<<PP, 192>>>(matrix, WsIn);
    k2_gemm<<<(PP + TP - 1) / TP, 256>>>();

    // device-wide segmented sort via packed keys (bits [12,40): 20 value + 8 k)
    k3p_pack<<<(int)((NTOT + 255) / 256), 256>>>();

    void* keysA = nullptr; void* keysB = nullptr; void* tmp = nullptr;
    cudaGetSymbolAddress(&keysA, g_keysA);
    cudaGetSymbolAddress(&keysB, g_keysB);
    cudaGetSymbolAddress(&tmp, g_cubtmp);

    cub::DoubleBuffer<unsigned long long> dbuf(
        (unsigned long long*)keysA, (unsigned long long*)keysB);
    size_t tmp_bytes = 0;
    cub::DeviceRadixSort::SortKeys(nullptr, tmp_bytes, dbuf, (int)NTOT,
                                   SORT_BEGIN_BIT, SORT_END_BIT);
    if (tmp_bytes > sizeof(g_cubtmp)) return;  // would be a config bug; fail loudly
    cub::DeviceRadixSort::SortKeys(tmp, tmp_bytes, dbuf, (int)NTOT,
                                   SORT_BEGIN_BIT, SORT_END_BIT);

    k3c_dot<<<KK, 1024>>>(dbuf.Current(), WdOut, out);
}

// round 11
// speedup vs baseline: 1.2035x; 1.2035x over previous
#include <cuda_runtime.h>
#include <math.h>
#include <cub/device/device_radix_sort.cuh>

#define DIMN 3
#define NPTS 30
#define KK   181
#define PP   24360          // 30*29*28
#define DE   190            // 9 + 181
#define RESTN 27
#define NTOT ((size_t)KK * PP)   // 4,409,160 elements

// ------------------------- device scratch (static, allowed) -------------------------
// +64 floats padding: K2's cp.async prefetch of the ragged last p-tile may read
// up to 63 elements past PP in the last row; keep that inside the allocation.
__device__ __align__(16) float g_vecT[(size_t)DE * PP + 64]; // (190, P) TRANSPOSED vec
__device__ float g_wsT[190 * 192];                      // Ws_out transposed, padded
__device__ float g_wdT[RESTN * KK];                     // WdIn transposed (27, 181)
__device__ __align__(16) unsigned int g_keysA[NTOT];    // packed (k | value>>8) keys
__device__ __align__(16) unsigned int g_keysB[NTOT];    // radix double buffer
__device__ __align__(16) unsigned char g_cubtmp[48 * 1024 * 1024]; // cub temp

// ------------------------- K0: transpose Ws_out -------------------------
__global__ void k0_transpose(const float* __restrict__ WsOut) {
    int j = blockIdx.x;          // 0..189
    int t = threadIdx.x;         // 0..191
    g_wsT[j * 192 + t] = (t < KK) ? WsOut[t * DE + j] : 0.0f;
}

// ------------------------- K0b: transpose Wd_in -------------------------
__global__ void k0b_transpose(const float* __restrict__ WdIn) {
    int m = blockIdx.x;          // 0..26
    int t = threadIdx.x;         // 0..191
    if (t < KK) g_wdT[m * KK + t] = WdIn[t * RESTN + m];
}

// ------------------------- K1: per-permutation vec rows (transposed store) ------------
__global__ void k1_vec(const float* __restrict__ matrix,
                       const float* __restrict__ WsIn) {
    __shared__ float mS[DIMN * NPTS];      // 90
    __shared__ float projS[DIMN][RESTN];   // 3x27
    __shared__ float gramS[9];

    const int p = blockIdx.x;
    const int t = threadIdx.x;             // 0..191

    // decode lexicographic permutation p -> (a,b,c)
    int a  = p / 812;                // 812 = 29*28
    int r  = p - a * 812;
    int bi = r / 28;
    int ci = r - bi * 28;
    int b  = bi + (bi >= a);
    int e0 = min(a, b), e1 = max(a, b);
    int c  = ci + (ci >= e0);
    c += (c >= e1);

    // sorted excluded triple for rest[]
    int s0 = min(a, min(b, c));
    int s2 = max(a, max(b, c));
    int s1 = a + b + c - s0 - s2;

    if (t < DIMN * NPTS) mS[t] = matrix[t];
    __syncthreads();

    if (t < DIMN * RESTN) {
        int i = t / RESTN, m = t - i * RESTN;
        int rm = m + (m >= s0); rm += (rm >= s1); rm += (rm >= s2);
        int ci_ = (i == 0) ? a : ((i == 1) ? b : c);
        projS[i][m] = mS[ci_] * mS[rm]
                    + mS[NPTS + ci_] * mS[NPTS + rm]
                    + mS[2 * NPTS + ci_] * mS[2 * NPTS + rm];
    } else if (t < DIMN * RESTN + 9) {
        int q = t - DIMN * RESTN;
        int i = q / 3, j = q - 3 * i;
        int ci_ = (i == 0) ? a : ((i == 1) ? b : c);
        int cj_ = (j == 0) ? a : ((j == 1) ? b : c);
        gramS[q] = mS[ci_] * mS[cj_]
                 + mS[NPTS + ci_] * mS[NPTS + cj_]
                 + mS[2 * NPTS + ci_] * mS[2 * NPTS + cj_];
    }
    __syncthreads();

    if (t < 9) g_vecT[(size_t)t * PP + p] = gramS[t];

    if (t < KK) {
        const int k = t;
        const float w0 = WsIn[k * 3 + 0];
        const float w1 = WsIn[k * 3 + 1];
        const float w2 = WsIn[k * 3 + 2];

        float v[32];
#pragma unroll
        for (int m = 0; m < RESTN; ++m)
            v[m] = fmaf(projS[2][m], w2, fmaf(projS[1][m], w1, projS[0][m] * w0));
        const float INF = __int_as_float(0x7f800000);
#pragma unroll
        for (int m = RESTN; m < 32; ++m) v[m] = INF;

        // fully-unrolled 32-element bitonic sort (ascending), registers only
#pragma unroll
        for (int size = 2; size <= 32; size <<= 1) {
#pragma unroll
            for (int stride = size >> 1; stride > 0; stride >>= 1) {
#pragma unroll
                for (int i = 0; i < 32; ++i) {
                    int j = i ^ stride;
                    if (j > i) {
                        bool up = ((i & size) == 0);
                        float x = v[i], y = v[j];
                        float lo = fminf(x, y), hi = fmaxf(x, y);
                        v[i] = up ? lo : hi;
                        v[j] = up ? hi : lo;
                    }
                }
            }
        }

        float e = 0.0f;
#pragma unroll
        for (int m = 0; m < RESTN; ++m)
            e = fmaf(g_wdT[m * KK + k], v[m], e);   // coalesced, L1-resident
        g_vecT[(size_t)(9 + k) * PP + p] = e;
    }
}

// ------------------------- K2: keys[k*PP+p] = pack(k, vec[p].Ws_out[k]) -----------------
// packed f32x2 FMA (pair along k) + cp.async double-buffered tile pipeline;
// epilogue twiddles + packs (k<<24 | tw>>8) and stores u32 keys directly.
#define TP 64
#define JC 19
#define NTILE (DE / JC)      // 10

__device__ __forceinline__ void ffma2(unsigned long long& d,
                                      unsigned long long a,
                                      unsigned long long b) {
    asm("fma.rn.f32x2 %0, %1, %2, %0;" : "+l"(d) : "l"(a), "l"(b));
}
__device__ __forceinline__ unsigned long long dup_f32(float x) {
    unsigned long long r;
    unsigned int u = __float_as_uint(x);
    asm("mov.b64 %0, {%1, %1};" : "=l"(r) : "r"(u));
    return r;
}
__device__ __forceinline__ void cp16(void* smem, const void* gmem) {
    unsigned int saddr = (unsigned int)__cvta_generic_to_shared(smem);
    asm volatile("cp.async.ca.shared.global [%0], [%1], 16;"
                 :: "r"(saddr), "l"(gmem));
}
__device__ __forceinline__ unsigned int pack_key(int k, float x) {
    unsigned int u = __float_as_uint(x);
    unsigned int tw = (u & 0x80000000u) ? ~u : (u | 0x80000000u);
    return ((unsigned int)k << 24) | (tw >> 8);
}

__global__ void __launch_bounds__(256)
k2_gemm() {
    __shared__ __align__(16) float vS[2][JC][TP];    // 2 x 4.9 KB
    __shared__ __align__(16) float wS[2][JC][192];   // 2 x 14.6 KB

    const int p0 = blockIdx.x * TP;
    const int t  = threadIdx.x;         // 256
    const int pt = t & 15;              // 16 p-threads (4 p each)
    const int kt = t >> 4;              // 16 k-threads (12 k each = 6 pairs)

    unsigned long long acc2[4][6];      // [p][k-pair]
#pragma unroll
    for (int r0 = 0; r0 < 4; ++r0)
#pragma unroll
        for (int cc = 0; cc < 6; ++cc) acc2[r0][cc] = 0ull;

    // ---- async tile loader: tile tt (j0 = tt*JC) into buffer b ----
    auto load_tile = [&](int tt, int b) {
        const int j0 = tt * JC;
        // vS: JC*TP/4 = 304 float4
        for (int idx = t; idx < JC * TP / 4; idx += 256) {
            int row = idx >> 4;          // /16
            int col = idx & 15;
            cp16(&vS[b][row][col * 4],
                 &g_vecT[(size_t)(j0 + row) * PP + p0 + col * 4]);
        }
        // wS: JC*192/4 = 912 float4
        for (int idx = t; idx < JC * 192 / 4; idx += 256) {
            int row = idx / 48;
            int col = idx - row * 48;
            cp16(&wS[b][row][col * 4],
                 &g_wsT[(j0 + row) * 192 + col * 4]);
        }
    };

    load_tile(0, 0);
    asm volatile("cp.async.commit_group;");

    for (int tt = 0; tt < NTILE; ++tt) {
        if (tt + 1 < NTILE) load_tile(tt + 1, (tt + 1) & 1);
        asm volatile("cp.async.commit_group;");
        asm volatile("cp.async.wait_group 1;");   // tile tt complete
        __syncthreads();

        const int b = tt & 1;
#pragma unroll
        for (int jj = 0; jj < JC; ++jj) {
            float4 rv = *reinterpret_cast<const float4*>(&vS[b][jj][pt * 4]);
            unsigned long long rr2[4] = {dup_f32(rv.x), dup_f32(rv.y),
                                         dup_f32(rv.z), dup_f32(rv.w)};
            const unsigned long long* wrow =
                reinterpret_cast<const unsigned long long*>(&wS[b][jj][0]);
            unsigned long long w2[6];
#pragma unroll
            for (int cc = 0; cc < 6; ++cc) w2[cc] = wrow[kt * 6 + cc];
#pragma unroll
            for (int cc = 0; cc < 6; ++cc)
#pragma unroll
                for (int r0 = 0; r0 < 4; ++r0)
                    ffma2(acc2[r0][cc], rr2[r0], w2[cc]);
        }
        __syncthreads();   // done reading buffer b before it is refilled
    }

    const bool full = (p0 + TP <= PP);
    // unpack: acc2[r0][cc] holds k = kt*12 + 2*cc (lo lane) and +1 (hi lane)
#pragma unroll
    for (int cc = 0; cc < 6; ++cc) {
#pragma unroll
        for (int half = 0; half < 2; ++half) {
            int k = kt * 12 + 2 * cc + half;
            if (k >= KK) continue;
            float a0, a1, a2, a3;
            if (half == 0) {
                a0 = __uint_as_float((unsigned int)(acc2[0][cc] & 0xffffffffull));
                a1 = __uint_as_float((unsigned int)(acc2[1][cc] & 0xffffffffull));
                a2 = __uint_as_float((unsigned int)(acc2[2][cc] & 0xffffffffull));
                a3 = __uint_as_float((unsigned int)(acc2[3][cc] & 0xffffffffull));
            } else {
                a0 = __uint_as_float((unsigned int)(acc2[0][cc] >> 32));
                a1 = __uint_as_float((unsigned int)(acc2[1][cc] >> 32));
                a2 = __uint_as_float((unsigned int)(acc2[2][cc] >> 32));
                a3 = __uint_as_float((unsigned int)(acc2[3][cc] >> 32));
            }
            size_t base = (size_t)k * PP + p0 + pt * 4;
            if (full) {
                uint4 kv = make_uint4(pack_key(k, a0), pack_key(k, a1),
                                      pack_key(k, a2), pack_key(k, a3));
                *reinterpret_cast<uint4*>(&g_keysA[base]) = kv;
            } else {
                float av[4] = {a0, a1, a2, a3};
#pragma unroll
                for (int r0 = 0; r0 < 4; ++r0) {
                    int p = p0 + pt * 4 + r0;
                    if (p < PP) g_keysA[(size_t)k * PP + p] = pack_key(k, av[r0]);
                }
            }
        }
    }
}

// ------------------------- K3c: rank-aligned weighted dot ------------------------------
// After the 32-bit sort, global position k*PP + r holds rank r of segment k.
// Value reconstructed from the low 24 key bits (midpoint of the truncated range).
__global__ void __launch_bounds__(1024)
k3c_dot(const unsigned int* __restrict__ keys,
        const float* __restrict__ WdOut, float* __restrict__ out) {
    __shared__ float red[32];
    const int k = blockIdx.x;
    const int t = threadIdx.x;
    const size_t base = (size_t)k * PP;

    float acc = 0.0f;
    for (int i = t; i < PP; i += 1024) {           // coalesced
        unsigned int tw = (keys[base + i] << 8) | 0x80u;
        unsigned int u = (tw & 0x80000000u) ? (tw ^ 0x80000000u) : ~tw;
        acc = fmaf(WdOut[base + i], __uint_as_float(u), acc);
    }

#pragma unroll
    for (int o = 16; o > 0; o >>= 1)
        acc += __shfl_down_sync(0xffffffffu, acc, o);
    if ((t & 31) == 0) red[t >> 5] = acc;
    __syncthreads();
    if (t < 32) {
        float x = red[t];
#pragma unroll
        for (int o = 16; o > 0; o >>= 1)
            x += __shfl_down_sync(0xffffffffu, x, o);
        if (t == 0) out[k] = x;
    }
}

// ------------------------- launch -------------------------
extern "C" void kernel_launch(void* const* d_in, const int* in_sizes, int n_in,
                              void* d_out, int out_size) {
    const float* matrix = (const float*)d_in[0];
    const float* WsIn   = (const float*)d_in[1];
    const float* WdIn   = (const float*)d_in[2];
    const float* WsOut  = (const float*)d_in[3];
    const float* WdOut  = (const float*)d_in[4];
    float* out = (float*)d_out;

    k0_transpose<<<DE, 192>>>(WsOut);
    k0b_transpose<<<RESTN, 192>>>(WdIn);
    k1_vec<<<PP, 192>>>(matrix, WsIn);
    k2_gemm<<<(PP + TP - 1) / TP, 256>>>();

    // device-wide segmented sort: u32 keys = (k<<24) | value_top24; L2-resident
    void* keysA = nullptr; void* keysB = nullptr; void* tmp = nullptr;
    cudaGetSymbolAddress(&keysA, g_keysA);
    cudaGetSymbolAddress(&keysB, g_keysB);
    cudaGetSymbolAddress(&tmp, g_cubtmp);

    cub::DoubleBuffer<unsigned int> dbuf(
        (unsigned int*)keysA, (unsigned int*)keysB);
    size_t tmp_bytes = 0;
    cub::DeviceRadixSort::SortKeys(nullptr, tmp_bytes, dbuf, (int)NTOT, 0, 32);
    if (tmp_bytes > sizeof(g_cubtmp)) return;  // would be a config bug; fail loudly
    cub::DeviceRadixSort::SortKeys(tmp, tmp_bytes, dbuf, (int)NTOT, 0, 32);

    k3c_dot<<<KK, 1024>>>(dbuf.Current(), WdOut, out);
}